// round 3
// baseline (speedup 1.0000x reference)
#include <cuda_runtime.h>
#include <math.h>

// ---------------- scratch (static device globals; no allocation) ----------------
__device__ float g_adp[1024 * 1024];              //   4 MB
__device__ float g_Mstack[1024 * 6144];           //  24 MB  [v, slot*1024+w]
__device__ float g_Xr[24576 * 1024];              // 100 MB  rows=(n,l,c), cols=v
__device__ float g_Z[150994944];                  // 604 MB  [24576, 6144]

// ---------------- adaptive adjacency: softmax(relu(nv1 @ nv2), axis=1) ----------
__global__ void adp_kernel(const float* __restrict__ nv1, const float* __restrict__ nv2) {
    int v = blockIdx.x;
    int tid = threadIdx.x;
    __shared__ float e1[10];
    __shared__ float red[256];
    if (tid < 10) e1[tid] = nv1[v * 10 + tid];
    __syncthreads();

    float vals[4];
#pragma unroll
    for (int q = 0; q < 4; q++) {
        int w = tid + q * 256;
        float s = 0.f;
#pragma unroll
        for (int t = 0; t < 10; t++) s += e1[t] * nv2[t * 1024 + w];
        vals[q] = fmaxf(s, 0.f);
    }
    // block max
    float m = fmaxf(fmaxf(vals[0], vals[1]), fmaxf(vals[2], vals[3]));
    red[tid] = m;
    __syncthreads();
    for (int s = 128; s > 0; s >>= 1) {
        if (tid < s) red[tid] = fmaxf(red[tid], red[tid + s]);
        __syncthreads();
    }
    m = red[0];
    __syncthreads();

    float e[4];
    float ssum = 0.f;
#pragma unroll
    for (int q = 0; q < 4; q++) { e[q] = expf(vals[q] - m); ssum += e[q]; }
    red[tid] = ssum;
    __syncthreads();
    for (int s = 128; s > 0; s >>= 1) {
        if (tid < s) red[tid] += red[tid + s];
        __syncthreads();
    }
    float denom = red[0];
#pragma unroll
    for (int q = 0; q < 4; q++) {
        int w = tid + q * 256;
        g_adp[v * 1024 + w] = e[q] / denom;
    }
}

// ---------------- copy A1, A2, adp into Mstack slots 0, 2, 4 --------------------
__global__ void copy_slots(const float* __restrict__ A1, const float* __restrict__ A2) {
    int g = blockIdx.x * 256 + threadIdx.x;       // 3 * 2^20 total
    int which = g >> 20;
    int rem = g & 0xFFFFF;
    int v = rem >> 10, w = rem & 1023;
    float val = (which == 0) ? A1[rem] : (which == 1) ? A2[rem] : g_adp[rem];
    int slot = which * 2;                          // 0, 2, 4
    g_Mstack[v * 6144 + slot * 1024 + w] = val;
}

// ---------------- generic 128x128x16 SGEMM body (8x8 per thread) ----------------
__device__ __forceinline__ void sgemm_body(
    const float* __restrict__ A, const float* __restrict__ B, float* __restrict__ C,
    int K, int lda, int ldb, int ldc)
{
    __shared__ float As[2][16][132];   // transposed, padded
    __shared__ float Bs[2][16][128];

    const int tid = threadIdx.x;
    const int bm = blockIdx.y * 128;
    const int bn = blockIdx.x * 128;
    const int tx = tid & 15;
    const int ty = tid >> 4;
    const int a_row = tid >> 2;             // 0..63
    const int a_col = (tid & 3) << 2;       // 0,4,8,12
    const int b_row = tid >> 5;             // 0..7
    const int b_col = (tid & 31) << 2;      // 0..124

    const float* Aptr = A + (size_t)bm * lda;
    const float* Bptr = B + bn;

    float acc[8][8];
#pragma unroll
    for (int i = 0; i < 8; i++)
#pragma unroll
        for (int j = 0; j < 8; j++) acc[i][j] = 0.f;

    // prologue: tile 0
    {
        float4 a0 = *(const float4*)(Aptr + (size_t)a_row * lda + a_col);
        float4 a1 = *(const float4*)(Aptr + (size_t)(a_row + 64) * lda + a_col);
        float4 b0 = *(const float4*)(Bptr + (size_t)b_row * ldb + b_col);
        float4 b1 = *(const float4*)(Bptr + (size_t)(b_row + 8) * ldb + b_col);
        As[0][a_col + 0][a_row] = a0.x; As[0][a_col + 1][a_row] = a0.y;
        As[0][a_col + 2][a_row] = a0.z; As[0][a_col + 3][a_row] = a0.w;
        As[0][a_col + 0][a_row + 64] = a1.x; As[0][a_col + 1][a_row + 64] = a1.y;
        As[0][a_col + 2][a_row + 64] = a1.z; As[0][a_col + 3][a_row + 64] = a1.w;
        *(float4*)&Bs[0][b_row][b_col] = b0;
        *(float4*)&Bs[0][b_row + 8][b_col] = b1;
    }
    __syncthreads();

    const int nt = K >> 4;
    for (int t = 0; t < nt; t++) {
        const int cur = t & 1;
        float4 a0, a1, b0, b1;
        if (t + 1 < nt) {
            int k0 = (t + 1) << 4;
            a0 = *(const float4*)(Aptr + (size_t)a_row * lda + k0 + a_col);
            a1 = *(const float4*)(Aptr + (size_t)(a_row + 64) * lda + k0 + a_col);
            b0 = *(const float4*)(Bptr + (size_t)(k0 + b_row) * ldb + b_col);
            b1 = *(const float4*)(Bptr + (size_t)(k0 + b_row + 8) * ldb + b_col);
        }
#pragma unroll
        for (int kk = 0; kk < 16; kk++) {
            float af[8], bf[8];
            *(float4*)(af)     = *(const float4*)&As[cur][kk][ty * 8];
            *(float4*)(af + 4) = *(const float4*)&As[cur][kk][ty * 8 + 4];
            *(float4*)(bf)     = *(const float4*)&Bs[cur][kk][tx * 8];
            *(float4*)(bf + 4) = *(const float4*)&Bs[cur][kk][tx * 8 + 4];
#pragma unroll
            for (int i = 0; i < 8; i++)
#pragma unroll
                for (int j = 0; j < 8; j++)
                    acc[i][j] = fmaf(af[i], bf[j], acc[i][j]);
        }
        if (t + 1 < nt) {
            const int nxt = cur ^ 1;
            As[nxt][a_col + 0][a_row] = a0.x; As[nxt][a_col + 1][a_row] = a0.y;
            As[nxt][a_col + 2][a_row] = a0.z; As[nxt][a_col + 3][a_row] = a0.w;
            As[nxt][a_col + 0][a_row + 64] = a1.x; As[nxt][a_col + 1][a_row + 64] = a1.y;
            As[nxt][a_col + 2][a_row + 64] = a1.z; As[nxt][a_col + 3][a_row + 64] = a1.w;
            *(float4*)&Bs[nxt][b_row][b_col] = b0;
            *(float4*)&Bs[nxt][b_row + 8][b_col] = b1;
        }
        __syncthreads();
    }

    float* Cp = C + (size_t)(bm + ty * 8) * ldc + bn + tx * 8;
#pragma unroll
    for (int i = 0; i < 8; i++) {
        *(float4*)(Cp + (size_t)i * ldc)     = make_float4(acc[i][0], acc[i][1], acc[i][2], acc[i][3]);
        *(float4*)(Cp + (size_t)i * ldc + 4) = make_float4(acc[i][4], acc[i][5], acc[i][6], acc[i][7]);
    }
}

// squares: A1^2 -> slot1, A2^2 -> slot3, adp^2 -> slot5 (batched on blockIdx.z)
__global__ __launch_bounds__(256, 2) void squares_kernel(const float* __restrict__ A1,
                                                         const float* __restrict__ A2) {
    const float* src = (blockIdx.z == 0) ? A1 : (blockIdx.z == 1) ? A2 : g_adp;
    int slot = blockIdx.z * 2 + 1;                // 1, 3, 5
    sgemm_body(src, src, g_Mstack + slot * 1024, 1024, 1024, 1024, 6144);
}

// main GEMM: Z[24576,6144] = Xr[24576,1024] @ Mstack[1024,6144]
__global__ __launch_bounds__(256, 2) void main_gemm_kernel() {
    sgemm_body(g_Xr, g_Mstack, g_Z, 1024, 1024, 6144, 6144);
}

// ---------------- transpose x [n,c,v,l] -> Xr rows=(n,l,c), cols=v --------------
__global__ void transpose_x(const float* __restrict__ x) {
    __shared__ float s[256 * 13];
    int n = blockIdx.z, c = blockIdx.y, v0 = blockIdx.x * 256;
    int tid = threadIdx.x;
    const float* src = x + ((size_t)(n * 32 + c) * 1024 + v0) * 12;
    for (int i = tid; i < 3072; i += 256) {
        int v = i / 12, l = i - v * 12;
        s[v * 13 + l] = src[i];
    }
    __syncthreads();
#pragma unroll
    for (int l = 0; l < 12; l++) {
        g_Xr[(size_t)((n * 12 + l) * 32 + c) * 1024 + v0 + tid] = s[tid * 13 + l];
    }
}

// ---------------- epilogue: 1x1 conv over 7 blocks, fused from Xr + Z -----------
// grid: (8 wtiles * 12 l, 64 n), 256 threads. Thread owns 4 o's x 4 w's.
__global__ __launch_bounds__(256) void epilogue_kernel(
    const float* __restrict__ W, const float* __restrict__ bias, float* __restrict__ out)
{
    __shared__ float Hs[32][128];
    __shared__ float Ws[32 * 32];
    int l = blockIdx.x % 12;
    int wt = blockIdx.x / 12;
    int n = blockIdx.y;
    int w0 = wt * 128;
    int tid = threadIdx.x;
    int og = tid >> 5;          // 0..7  -> o = og*4 + j
    int wl = tid & 31;          // w = w0 + wl + 32*i

    int rbase = (n * 12 + l) * 32;

    float acc[4][4];
#pragma unroll
    for (int j = 0; j < 4; j++) {
        float bj = bias[og * 4 + j];
#pragma unroll
        for (int i = 0; i < 4; i++) acc[j][i] = bj;
    }

    for (int k = 0; k < 7; k++) {
        // load H chunk [32 c, 128 w]
        if (k == 0) {
            for (int i = tid; i < 4096; i += 256) {
                int c = i >> 7, w = i & 127;
                Hs[c][w] = g_Xr[(size_t)(rbase + c) * 1024 + w0 + w];
            }
        } else {
            for (int i = tid; i < 4096; i += 256) {
                int c = i >> 7, w = i & 127;
                Hs[c][w] = g_Z[(size_t)(rbase + c) * 6144 + (k - 1) * 1024 + w0 + w];
            }
        }
        // load W block [32 o, 32 c]
        for (int i = tid; i < 1024; i += 256)
            Ws[i] = W[(i >> 5) * 224 + 32 * k + (i & 31)];
        __syncthreads();

#pragma unroll 4
        for (int c = 0; c < 32; c++) {
            float wv[4], hv[4];
#pragma unroll
            for (int j = 0; j < 4; j++) wv[j] = Ws[(og * 4 + j) * 32 + c];
#pragma unroll
            for (int i = 0; i < 4; i++) hv[i] = Hs[c][wl + 32 * i];
#pragma unroll
            for (int j = 0; j < 4; j++)
#pragma unroll
                for (int i = 0; i < 4; i++)
                    acc[j][i] = fmaf(wv[j], hv[i], acc[j][i]);
        }
        __syncthreads();
    }

#pragma unroll
    for (int j = 0; j < 4; j++) {
        int o = og * 4 + j;
#pragma unroll
        for (int i = 0; i < 4; i++) {
            int w = w0 + wl + 32 * i;
            out[((size_t)(n * 32 + o) * 1024 + w) * 12 + l] = acc[j][i];
        }
    }
}

// -------------------------------- launch ----------------------------------------
extern "C" void kernel_launch(void* const* d_in, const int* in_sizes, int n_in,
                              void* d_out, int out_size) {
    const float* x   = (const float*)d_in[0];
    const float* A1  = (const float*)d_in[1];
    const float* A2  = (const float*)d_in[2];
    const float* nv1 = (const float*)d_in[3];
    const float* nv2 = (const float*)d_in[4];
    const float* W   = (const float*)d_in[5];
    const float* b   = (const float*)d_in[6];
    float* out = (float*)d_out;

    adp_kernel<<<1024, 256>>>(nv1, nv2);
    copy_slots<<<(3 * 1024 * 1024) / 256, 256>>>(A1, A2);
    {
        dim3 g(8, 8, 3);
        squares_kernel<<<g, 256>>>(A1, A2);
    }
    transpose_x<<<dim3(4, 32, 64), 256>>>(x);
    main_gemm_kernel<<<dim3(48, 192), 256>>>();
    epilogue_kernel<<<dim3(96, 64), 256>>>(W, b, out);
}

// round 4
// speedup vs baseline: 1.6238x; 1.6238x over previous
#include <cuda_runtime.h>
#include <math.h>

// ---------------- scratch (static device globals; no allocation) ----------------
__device__ float g_adp[1024 * 1024];              //   4 MB
__device__ float g_Mstack[1024 * 6144];           //  24 MB  [v, slot*1024+w]
__device__ float g_Xr[24576 * 1024];              // 100 MB  rows=(n,l,c), cols=v
__device__ float g_Z[150994944];                  // 604 MB  [24576, 6144]

// ---------------- adaptive adjacency: softmax(relu(nv1 @ nv2), axis=1) ----------
__global__ void adp_kernel(const float* __restrict__ nv1, const float* __restrict__ nv2) {
    int v = blockIdx.x;
    int tid = threadIdx.x;
    __shared__ float e1[10];
    __shared__ float red[256];
    if (tid < 10) e1[tid] = nv1[v * 10 + tid];
    __syncthreads();

    float vals[4];
#pragma unroll
    for (int q = 0; q < 4; q++) {
        int w = tid + q * 256;
        float s = 0.f;
#pragma unroll
        for (int t = 0; t < 10; t++) s += e1[t] * nv2[t * 1024 + w];
        vals[q] = fmaxf(s, 0.f);
    }
    // block max
    float m = fmaxf(fmaxf(vals[0], vals[1]), fmaxf(vals[2], vals[3]));
    red[tid] = m;
    __syncthreads();
    for (int s = 128; s > 0; s >>= 1) {
        if (tid < s) red[tid] = fmaxf(red[tid], red[tid + s]);
        __syncthreads();
    }
    m = red[0];
    __syncthreads();

    float e[4];
    float ssum = 0.f;
#pragma unroll
    for (int q = 0; q < 4; q++) { e[q] = expf(vals[q] - m); ssum += e[q]; }
    red[tid] = ssum;
    __syncthreads();
    for (int s = 128; s > 0; s >>= 1) {
        if (tid < s) red[tid] += red[tid + s];
        __syncthreads();
    }
    float denom = red[0];
#pragma unroll
    for (int q = 0; q < 4; q++) {
        int w = tid + q * 256;
        g_adp[v * 1024 + w] = e[q] / denom;
    }
}

// ---------------- copy A1, A2, adp into Mstack slots 0, 2, 4 --------------------
__global__ void copy_slots(const float* __restrict__ A1, const float* __restrict__ A2) {
    int g = blockIdx.x * 256 + threadIdx.x;       // 3 * 2^20 total
    int which = g >> 20;
    int rem = g & 0xFFFFF;
    int v = rem >> 10, w = rem & 1023;
    float val = (which == 0) ? A1[rem] : (which == 1) ? A2[rem] : g_adp[rem];
    int slot = which * 2;                          // 0, 2, 4
    g_Mstack[v * 6144 + slot * 1024 + w] = val;
}

// ---------------- generic 128x128x16 SGEMM body (8x8 per thread) ----------------
__device__ __forceinline__ void sgemm_body(
    const float* __restrict__ A, const float* __restrict__ B, float* __restrict__ C,
    int K, int lda, int ldb, int ldc)
{
    __shared__ float As[2][16][132];   // transposed, padded
    __shared__ float Bs[2][16][128];

    const int tid = threadIdx.x;
    const int bm = blockIdx.y * 128;
    const int bn = blockIdx.x * 128;
    const int tx = tid & 15;
    const int ty = tid >> 4;
    const int a_row = tid >> 2;             // 0..63
    const int a_col = (tid & 3) << 2;       // 0,4,8,12
    const int b_row = tid >> 5;             // 0..7
    const int b_col = (tid & 31) << 2;      // 0..124

    const float* Aptr = A + (size_t)bm * lda;
    const float* Bptr = B + bn;

    float acc[8][8];
#pragma unroll
    for (int i = 0; i < 8; i++)
#pragma unroll
        for (int j = 0; j < 8; j++) acc[i][j] = 0.f;

    // prologue: tile 0
    {
        float4 a0 = *(const float4*)(Aptr + (size_t)a_row * lda + a_col);
        float4 a1 = *(const float4*)(Aptr + (size_t)(a_row + 64) * lda + a_col);
        float4 b0 = *(const float4*)(Bptr + (size_t)b_row * ldb + b_col);
        float4 b1 = *(const float4*)(Bptr + (size_t)(b_row + 8) * ldb + b_col);
        As[0][a_col + 0][a_row] = a0.x; As[0][a_col + 1][a_row] = a0.y;
        As[0][a_col + 2][a_row] = a0.z; As[0][a_col + 3][a_row] = a0.w;
        As[0][a_col + 0][a_row + 64] = a1.x; As[0][a_col + 1][a_row + 64] = a1.y;
        As[0][a_col + 2][a_row + 64] = a1.z; As[0][a_col + 3][a_row + 64] = a1.w;
        *(float4*)&Bs[0][b_row][b_col] = b0;
        *(float4*)&Bs[0][b_row + 8][b_col] = b1;
    }
    __syncthreads();

    const int nt = K >> 4;
    for (int t = 0; t < nt; t++) {
        const int cur = t & 1;
        float4 a0, a1, b0, b1;
        if (t + 1 < nt) {
            int k0 = (t + 1) << 4;
            a0 = *(const float4*)(Aptr + (size_t)a_row * lda + k0 + a_col);
            a1 = *(const float4*)(Aptr + (size_t)(a_row + 64) * lda + k0 + a_col);
            b0 = *(const float4*)(Bptr + (size_t)(k0 + b_row) * ldb + b_col);
            b1 = *(const float4*)(Bptr + (size_t)(k0 + b_row + 8) * ldb + b_col);
        }
#pragma unroll
        for (int kk = 0; kk < 16; kk++) {
            float af[8], bf[8];
            *(float4*)(af)     = *(const float4*)&As[cur][kk][ty * 8];
            *(float4*)(af + 4) = *(const float4*)&As[cur][kk][ty * 8 + 4];
            *(float4*)(bf)     = *(const float4*)&Bs[cur][kk][tx * 8];
            *(float4*)(bf + 4) = *(const float4*)&Bs[cur][kk][tx * 8 + 4];
#pragma unroll
            for (int i = 0; i < 8; i++)
#pragma unroll
                for (int j = 0; j < 8; j++)
                    acc[i][j] = fmaf(af[i], bf[j], acc[i][j]);
        }
        if (t + 1 < nt) {
            const int nxt = cur ^ 1;
            As[nxt][a_col + 0][a_row] = a0.x; As[nxt][a_col + 1][a_row] = a0.y;
            As[nxt][a_col + 2][a_row] = a0.z; As[nxt][a_col + 3][a_row] = a0.w;
            As[nxt][a_col + 0][a_row + 64] = a1.x; As[nxt][a_col + 1][a_row + 64] = a1.y;
            As[nxt][a_col + 2][a_row + 64] = a1.z; As[nxt][a_col + 3][a_row + 64] = a1.w;
            *(float4*)&Bs[nxt][b_row][b_col] = b0;
            *(float4*)&Bs[nxt][b_row + 8][b_col] = b1;
        }
        __syncthreads();
    }

    float* Cp = C + (size_t)(bm + ty * 8) * ldc + bn + tx * 8;
#pragma unroll
    for (int i = 0; i < 8; i++) {
        *(float4*)(Cp + (size_t)i * ldc)     = make_float4(acc[i][0], acc[i][1], acc[i][2], acc[i][3]);
        *(float4*)(Cp + (size_t)i * ldc + 4) = make_float4(acc[i][4], acc[i][5], acc[i][6], acc[i][7]);
    }
}

// squares: A1^2 -> slot1, A2^2 -> slot3, adp^2 -> slot5 (batched on blockIdx.z)
__global__ __launch_bounds__(256, 2) void squares_kernel(const float* __restrict__ A1,
                                                         const float* __restrict__ A2) {
    const float* src = (blockIdx.z == 0) ? A1 : (blockIdx.z == 1) ? A2 : g_adp;
    int slot = blockIdx.z * 2 + 1;                // 1, 3, 5
    sgemm_body(src, src, g_Mstack + slot * 1024, 1024, 1024, 1024, 6144);
}

// main GEMM: Z[24576,6144] = Xr[24576,1024] @ Mstack[1024,6144]
__global__ __launch_bounds__(256, 2) void main_gemm_kernel() {
    sgemm_body(g_Xr, g_Mstack, g_Z, 1024, 1024, 6144, 6144);
}

// ---------------- transpose x [n,c,v,l] -> Xr rows=(n,l,c), cols=v --------------
__global__ void transpose_x(const float* __restrict__ x) {
    __shared__ float s[256 * 13];
    int n = blockIdx.z, c = blockIdx.y, v0 = blockIdx.x * 256;
    int tid = threadIdx.x;
    const float* src = x + ((size_t)(n * 32 + c) * 1024 + v0) * 12;
    for (int i = tid; i < 3072; i += 256) {
        int v = i / 12, l = i - v * 12;
        s[v * 13 + l] = src[i];
    }
    __syncthreads();
#pragma unroll
    for (int l = 0; l < 12; l++) {
        g_Xr[(size_t)((n * 12 + l) * 32 + c) * 1024 + v0 + tid] = s[tid * 13 + l];
    }
}

// ---------------- epilogue: 1x1 conv over 7 blocks, fused from Xr + Z -----------
// grid: (8 wtiles * 12 l, 64 n), 256 threads. Thread owns 4 o's x 4 w's.
__global__ __launch_bounds__(256) void epilogue_kernel(
    const float* __restrict__ W, const float* __restrict__ bias, float* __restrict__ out)
{
    __shared__ float Hs[32][128];
    __shared__ float Ws[32 * 32];
    int l = blockIdx.x % 12;
    int wt = blockIdx.x / 12;
    int n = blockIdx.y;
    int w0 = wt * 128;
    int tid = threadIdx.x;
    int og = tid >> 5;          // 0..7  -> o = og*4 + j
    int wl = tid & 31;          // w = w0 + wl + 32*i

    int rbase = (n * 12 + l) * 32;

    float acc[4][4];
#pragma unroll
    for (int j = 0; j < 4; j++) {
        float bj = bias[og * 4 + j];
#pragma unroll
        for (int i = 0; i < 4; i++) acc[j][i] = bj;
    }

    for (int k = 0; k < 7; k++) {
        // load H chunk [32 c, 128 w]
        if (k == 0) {
            for (int i = tid; i < 4096; i += 256) {
                int c = i >> 7, w = i & 127;
                Hs[c][w] = g_Xr[(size_t)(rbase + c) * 1024 + w0 + w];
            }
        } else {
            for (int i = tid; i < 4096; i += 256) {
                int c = i >> 7, w = i & 127;
                Hs[c][w] = g_Z[(size_t)(rbase + c) * 6144 + (k - 1) * 1024 + w0 + w];
            }
        }
        // load W block [32 o, 32 c]
        for (int i = tid; i < 1024; i += 256)
            Ws[i] = W[(i >> 5) * 224 + 32 * k + (i & 31)];
        __syncthreads();

#pragma unroll 4
        for (int c = 0; c < 32; c++) {
            float wv[4], hv[4];
#pragma unroll
            for (int j = 0; j < 4; j++) wv[j] = Ws[(og * 4 + j) * 32 + c];
#pragma unroll
            for (int i = 0; i < 4; i++) hv[i] = Hs[c][wl + 32 * i];
#pragma unroll
            for (int j = 0; j < 4; j++)
#pragma unroll
                for (int i = 0; i < 4; i++)
                    acc[j][i] = fmaf(wv[j], hv[i], acc[j][i]);
        }
        __syncthreads();
    }

#pragma unroll
    for (int j = 0; j < 4; j++) {
        int o = og * 4 + j;
#pragma unroll
        for (int i = 0; i < 4; i++) {
            int w = w0 + wl + 32 * i;
            out[((size_t)(n * 32 + o) * 1024 + w) * 12 + l] = acc[j][i];
        }
    }
}

// -------------------------------- launch ----------------------------------------
extern "C" void kernel_launch(void* const* d_in, const int* in_sizes, int n_in,
                              void* d_out, int out_size) {
    const float* x   = (const float*)d_in[0];
    const float* A1  = (const float*)d_in[1];
    const float* A2  = (const float*)d_in[2];
    const float* nv1 = (const float*)d_in[3];
    const float* nv2 = (const float*)d_in[4];
    const float* W   = (const float*)d_in[5];
    const float* b   = (const float*)d_in[6];
    float* out = (float*)d_out;

    adp_kernel<<<1024, 256>>>(nv1, nv2);
    copy_slots<<<(3 * 1024 * 1024) / 256, 256>>>(A1, A2);
    {
        dim3 g(8, 8, 3);
        squares_kernel<<<g, 256>>>(A1, A2);
    }
    transpose_x<<<dim3(4, 32, 64), 256>>>(x);
    main_gemm_kernel<<<dim3(48, 192), 256>>>();
    epilogue_kernel<<<dim3(96, 64), 256>>>(W, b, out);
}

// round 9
// speedup vs baseline: 3.3518x; 2.0642x over previous
#include <cuda_runtime.h>
#include <cuda_bf16.h>
#include <math.h>
#include <cstdint>

// ---------------- scratch (static device globals; no allocation) ----------------
__device__ float g_adp[1024 * 1024];                                  //   4 MB
__device__ float g_MstackT[6144 * 1024];                              //  24 MB [n=slot*1024+w, v]
__device__ __align__(16) __nv_bfloat16 g_Mcat[6144 * 3072];           //  37.7 MB [n, kcat]
__device__ float g_Xr[24576 * 1024];                                  // 100 MB rows=(n,l,c), cols=v
__device__ __align__(16) __nv_bfloat16 g_Xcat[(size_t)24576 * 3072];  // 151 MB [row, kcat]
__device__ float g_Z[150994944];                                      // 604 MB [24576, 6144]

// ================= PTX helpers (baseline sm_80-class: cp.async/ldmatrix/mma) ====
__device__ __forceinline__ uint32_t smem_u32(const void* p) {
    uint32_t a;
    asm("{ .reg .u64 t; cvta.to.shared.u64 t, %1; cvt.u32.u64 %0, t; }" : "=r"(a) : "l"(p));
    return a;
}
__device__ __forceinline__ void cp_async16(uint32_t dst, const void* src) {
    asm volatile("cp.async.cg.shared.global [%0], [%1], 16;" :: "r"(dst), "l"(src));
}
__device__ __forceinline__ void cp_commit() {
    asm volatile("cp.async.commit_group;" ::: "memory");
}
template <int N>
__device__ __forceinline__ void cp_wait() {
    asm volatile("cp.async.wait_group %0;" :: "n"(N) : "memory");
}
__device__ __forceinline__ void ldsm_x4(uint32_t* r, uint32_t addr) {
    asm volatile("ldmatrix.sync.aligned.m8n8.x4.shared.b16 {%0,%1,%2,%3}, [%4];"
        : "=r"(r[0]), "=r"(r[1]), "=r"(r[2]), "=r"(r[3]) : "r"(addr));
}
__device__ __forceinline__ void mma_16816(float* c, const uint32_t* a, uint32_t b0, uint32_t b1) {
    asm volatile("mma.sync.aligned.m16n8k16.row.col.f32.bf16.bf16.f32 "
        "{%0,%1,%2,%3}, {%4,%5,%6,%7}, {%8,%9}, {%0,%1,%2,%3};"
        : "+f"(c[0]), "+f"(c[1]), "+f"(c[2]), "+f"(c[3])
        : "r"(a[0]), "r"(a[1]), "r"(a[2]), "r"(a[3]), "r"(b0), "r"(b1));
}
__device__ __forceinline__ uint32_t swz128(uint32_t o) { return o ^ ((o >> 3) & 0x70); }

// ---------------- adaptive adjacency: softmax(relu(nv1 @ nv2), axis=1) ----------
__global__ void adp_kernel(const float* __restrict__ nv1, const float* __restrict__ nv2) {
    int v = blockIdx.x;
    int tid = threadIdx.x;
    __shared__ float e1[10];
    __shared__ float red[256];
    if (tid < 10) e1[tid] = nv1[v * 10 + tid];
    __syncthreads();

    float vals[4];
#pragma unroll
    for (int q = 0; q < 4; q++) {
        int w = tid + q * 256;
        float s = 0.f;
#pragma unroll
        for (int t = 0; t < 10; t++) s += e1[t] * nv2[t * 1024 + w];
        vals[q] = fmaxf(s, 0.f);
    }
    float m = fmaxf(fmaxf(vals[0], vals[1]), fmaxf(vals[2], vals[3]));
    red[tid] = m;
    __syncthreads();
    for (int s = 128; s > 0; s >>= 1) {
        if (tid < s) red[tid] = fmaxf(red[tid], red[tid + s]);
        __syncthreads();
    }
    m = red[0];
    __syncthreads();

    float e[4];
    float ssum = 0.f;
#pragma unroll
    for (int q = 0; q < 4; q++) { e[q] = expf(vals[q] - m); ssum += e[q]; }
    red[tid] = ssum;
    __syncthreads();
    for (int s = 128; s > 0; s >>= 1) {
        if (tid < s) red[tid] += red[tid + s];
        __syncthreads();
    }
    float denom = red[0];
#pragma unroll
    for (int q = 0; q < 4; q++) {
        int w = tid + q * 256;
        g_adp[v * 1024 + w] = e[q] / denom;
    }
}

// -------- transposed copy: MstackT[slot*1024+w][v] = M[v][w], slots 0,2,4 -------
__global__ void copy_slots_T(const float* __restrict__ A1, const float* __restrict__ A2) {
    __shared__ float ts[32][33];
    int which = blockIdx.z;
    const float* src = (which == 0) ? A1 : (which == 1) ? A2 : g_adp;
    int v0 = blockIdx.y * 32, w0 = blockIdx.x * 32;
    int tx = threadIdx.x, ty = threadIdx.y;  // 32 x 8
#pragma unroll
    for (int q = 0; q < 4; q++)
        ts[ty + q * 8][tx] = src[(size_t)(v0 + ty + q * 8) * 1024 + w0 + tx];
    __syncthreads();
    size_t base = ((size_t)(which * 2) * 1024 + w0) * 1024 + v0;
#pragma unroll
    for (int q = 0; q < 4; q++)
        g_MstackT[base + (size_t)(ty + q * 8) * 1024 + tx] = ts[tx][ty + q * 8];
}

// ---------------- generic 128x128x16 fp32 SGEMM body (squares only) -------------
__device__ __forceinline__ void sgemm_body(
    const float* __restrict__ A, const float* __restrict__ B, float* __restrict__ C,
    int K, int lda, int ldb, int ldc)
{
    __shared__ float As[2][16][132];
    __shared__ float Bs[2][16][128];

    const int tid = threadIdx.x;
    const int bm = blockIdx.y * 128;
    const int bn = blockIdx.x * 128;
    const int tx = tid & 15;
    const int ty = tid >> 4;
    const int a_row = tid >> 2;
    const int a_col = (tid & 3) << 2;
    const int b_row = tid >> 5;
    const int b_col = (tid & 31) << 2;

    const float* Aptr = A + (size_t)bm * lda;
    const float* Bptr = B + bn;

    float acc[8][8];
#pragma unroll
    for (int i = 0; i < 8; i++)
#pragma unroll
        for (int j = 0; j < 8; j++) acc[i][j] = 0.f;

    {
        float4 a0 = *(const float4*)(Aptr + (size_t)a_row * lda + a_col);
        float4 a1 = *(const float4*)(Aptr + (size_t)(a_row + 64) * lda + a_col);
        float4 b0 = *(const float4*)(Bptr + (size_t)b_row * ldb + b_col);
        float4 b1 = *(const float4*)(Bptr + (size_t)(b_row + 8) * ldb + b_col);
        As[0][a_col + 0][a_row] = a0.x; As[0][a_col + 1][a_row] = a0.y;
        As[0][a_col + 2][a_row] = a0.z; As[0][a_col + 3][a_row] = a0.w;
        As[0][a_col + 0][a_row + 64] = a1.x; As[0][a_col + 1][a_row + 64] = a1.y;
        As[0][a_col + 2][a_row + 64] = a1.z; As[0][a_col + 3][a_row + 64] = a1.w;
        *(float4*)&Bs[0][b_row][b_col] = b0;
        *(float4*)&Bs[0][b_row + 8][b_col] = b1;
    }
    __syncthreads();

    const int nt = K >> 4;
    for (int t = 0; t < nt; t++) {
        const int cur = t & 1;
        float4 a0, a1, b0, b1;
        if (t + 1 < nt) {
            int k0 = (t + 1) << 4;
            a0 = *(const float4*)(Aptr + (size_t)a_row * lda + k0 + a_col);
            a1 = *(const float4*)(Aptr + (size_t)(a_row + 64) * lda + k0 + a_col);
            b0 = *(const float4*)(Bptr + (size_t)(k0 + b_row) * ldb + b_col);
            b1 = *(const float4*)(Bptr + (size_t)(k0 + b_row + 8) * ldb + b_col);
        }
#pragma unroll
        for (int kk = 0; kk < 16; kk++) {
            float af[8], bf[8];
            *(float4*)(af)     = *(const float4*)&As[cur][kk][ty * 8];
            *(float4*)(af + 4) = *(const float4*)&As[cur][kk][ty * 8 + 4];
            *(float4*)(bf)     = *(const float4*)&Bs[cur][kk][tx * 8];
            *(float4*)(bf + 4) = *(const float4*)&Bs[cur][kk][tx * 8 + 4];
#pragma unroll
            for (int i = 0; i < 8; i++)
#pragma unroll
                for (int j = 0; j < 8; j++)
                    acc[i][j] = fmaf(af[i], bf[j], acc[i][j]);
        }
        if (t + 1 < nt) {
            const int nxt = cur ^ 1;
            As[nxt][a_col + 0][a_row] = a0.x; As[nxt][a_col + 1][a_row] = a0.y;
            As[nxt][a_col + 2][a_row] = a0.z; As[nxt][a_col + 3][a_row] = a0.w;
            As[nxt][a_col + 0][a_row + 64] = a1.x; As[nxt][a_col + 1][a_row + 64] = a1.y;
            As[nxt][a_col + 2][a_row + 64] = a1.z; As[nxt][a_col + 3][a_row + 64] = a1.w;
            *(float4*)&Bs[nxt][b_row][b_col] = b0;
            *(float4*)&Bs[nxt][b_row + 8][b_col] = b1;
        }
        __syncthreads();
    }

    float* Cp = C + (size_t)(bm + ty * 8) * ldc + bn + tx * 8;
#pragma unroll
    for (int i = 0; i < 8; i++) {
        *(float4*)(Cp + (size_t)i * ldc)     = make_float4(acc[i][0], acc[i][1], acc[i][2], acc[i][3]);
        *(float4*)(Cp + (size_t)i * ldc + 4) = make_float4(acc[i][4], acc[i][5], acc[i][6], acc[i][7]);
    }
}

// squares on transposed slots: (A^2)^T = A^T @ A^T; slots 0,2,4 -> 1,3,5
__global__ __launch_bounds__(256, 2) void squares_T_kernel() {
    int slot = blockIdx.z * 2;  // 0, 2, 4
    const float* src = g_MstackT + (size_t)slot * 1024 * 1024;
    float* dst = g_MstackT + (size_t)(slot + 1) * 1024 * 1024;
    sgemm_body(src, src, dst, 1024, 1024, 1024, 1024);
}

// bf16 hi/lo split of MstackT -> Mcat = [Mh | Mh | Ml] along k
__global__ void convert_m() {
    size_t i = (size_t)blockIdx.x * 256 + threadIdx.x;   // 6144*1024 elems
    int row = (int)(i >> 10), v = (int)(i & 1023);
    float val = g_MstackT[i];
    __nv_bfloat16 h = __float2bfloat16(val);
    __nv_bfloat16 lo = __float2bfloat16(val - __bfloat162float(h));
    size_t b = (size_t)row * 3072 + v;
    g_Mcat[b] = h;
    g_Mcat[b + 1024] = h;
    g_Mcat[b + 2048] = lo;
}

// ------- transpose x [n,c,v,l] -> Xr rows=(n,l,c); Xcat = [Xh | Xl | Xh] --------
__global__ void transpose_x(const float* __restrict__ x) {
    __shared__ float s[256 * 13];
    int n = blockIdx.z, c = blockIdx.y, v0 = blockIdx.x * 256;
    int tid = threadIdx.x;
    const float* src = x + ((size_t)(n * 32 + c) * 1024 + v0) * 12;
    for (int i = tid; i < 3072; i += 256) {
        int v = i / 12, l = i - v * 12;
        s[v * 13 + l] = src[i];
    }
    __syncthreads();
#pragma unroll
    for (int l = 0; l < 12; l++) {
        int row = (n * 12 + l) * 32 + c;
        float v = s[tid * 13 + l];
        __nv_bfloat16 h = __float2bfloat16(v);
        __nv_bfloat16 lo = __float2bfloat16(v - __bfloat162float(h));
        g_Xr[(size_t)row * 1024 + v0 + tid] = v;
        size_t xb = (size_t)row * 3072 + v0 + tid;
        g_Xcat[xb] = h;
        g_Xcat[xb + 1024] = lo;
        g_Xcat[xb + 2048] = h;
    }
}

// =============== main GEMM: bf16 mma.sync, CTA 128x256, K=3072, BK=64 ===========
// Z[24576,6144] = Xcat[24576,3072] @ Mcat[6144,3072]^T  (row.col)
// 512 threads (16 warps, 2x8), warp tile 64x32, 3-stage cp.async pipeline.
static constexpr int GK_TILES = 3072 / 64;   // 48
static constexpr int STAGE_BYTES = 49152;    // A 16K + B 32K
static constexpr int GEMM_SMEM = 3 * STAGE_BYTES;

__global__ __launch_bounds__(512, 1) void gemm_mma() {
    extern __shared__ char smem[];
    const uint32_t sb = smem_u32(smem);
    const int tid = threadIdx.x;
    const int warp = tid >> 5, lane = tid & 31;
    const int bm = blockIdx.y * 128;
    const int bn = blockIdx.x * 256;
    const int wm = (warp >> 3) * 64;   // 0 / 64
    const int wn = (warp & 7) * 32;    // 0..224

    const __nv_bfloat16* Ag = g_Xcat + (size_t)bm * 3072;
    const __nv_bfloat16* Bg = g_Mcat + (size_t)bn * 3072;

    // per-thread copy coords (fixed across stages)
    const int ar0 = tid >> 3, ac = tid & 7;           // A: 2 chunks (rows ar0, ar0+64)
    const uint32_t aso0 = swz128((uint32_t)(ar0 * 128 + ac * 16));
    const uint32_t aso1 = swz128((uint32_t)((ar0 + 64) * 128 + ac * 16));
    const size_t ag0 = (size_t)ar0 * 3072 + ac * 8;

    auto load_stage = [&](int t, int s) {
        const uint32_t ab = sb + s * STAGE_BYTES;
        const uint32_t bb = ab + 16384;
        const __nv_bfloat16* a = Ag + t * 64;
        const __nv_bfloat16* b = Bg + t * 64;
        cp_async16(ab + aso0, a + ag0);
        cp_async16(ab + aso1, a + ag0 + (size_t)64 * 3072);
#pragma unroll
        for (int i = 0; i < 4; i++)
            cp_async16(bb + swz128((uint32_t)((ar0 + 64 * i) * 128 + ac * 16)),
                       b + ag0 + (size_t)(64 * i) * 3072);
    };

    float acc[4][4][4];
#pragma unroll
    for (int mi = 0; mi < 4; mi++)
#pragma unroll
        for (int ni = 0; ni < 4; ni++)
#pragma unroll
            for (int q = 0; q < 4; q++) acc[mi][ni][q] = 0.f;

    load_stage(0, 0); cp_commit();
    load_stage(1, 1); cp_commit();

    for (int t = 0; t < GK_TILES; t++) {
        const int s = t % 3;
        cp_wait<1>();
        __syncthreads();
        if (t + 2 < GK_TILES) load_stage(t + 2, (t + 2) % 3);
        cp_commit();   // empty groups at tail keep the pending count honest

        const uint32_t ab = sb + s * STAGE_BYTES;
        const uint32_t bb = ab + 16384;
        const int lrow = lane & 15, lch = (lane >> 4) * 16;

#pragma unroll
        for (int kk = 0; kk < 4; kk++) {      // 4 x k16 chunks = full BK=64
            uint32_t b[2][4];
#pragma unroll
            for (int nj = 0; nj < 2; nj++) {
                uint32_t addr = bb + swz128((uint32_t)((wn + nj * 16 + lrow) * 128 + kk * 32 + lch));
                ldsm_x4(b[nj], addr);
            }
#pragma unroll
            for (int mi = 0; mi < 4; mi++) {
                uint32_t a[4];
                uint32_t addr = ab + swz128((uint32_t)((wm + mi * 16 + lrow) * 128 + kk * 32 + lch));
                ldsm_x4(a, addr);
#pragma unroll
                for (int ni = 0; ni < 4; ni++)
                    mma_16816(acc[mi][ni], a, b[ni >> 1][ni & 1], b[ni >> 1][(ni & 1) + 2]);
            }
        }
        __syncthreads();
    }

    // writeback: float2 per frag half-row
    const int crow = lane >> 2, ccol = (lane & 3) * 2;
#pragma unroll
    for (int mi = 0; mi < 4; mi++) {
#pragma unroll
        for (int ni = 0; ni < 4; ni++) {
            float* zp = g_Z + (size_t)(bm + wm + mi * 16 + crow) * 6144 + bn + wn + ni * 8 + ccol;
            *(float2*)zp = make_float2(acc[mi][ni][0], acc[mi][ni][1]);
            *(float2*)(zp + (size_t)8 * 6144) = make_float2(acc[mi][ni][2], acc[mi][ni][3]);
        }
    }
}

// ---------------- epilogue: 1x1 conv over 7 blocks, fused from Xr + Z -----------
__global__ __launch_bounds__(256) void epilogue_kernel(
    const float* __restrict__ W, const float* __restrict__ bias, float* __restrict__ out)
{
    __shared__ float Hs[32][128];
    __shared__ float Ws[32 * 32];
    int l = blockIdx.x % 12;
    int wt = blockIdx.x / 12;
    int n = blockIdx.y;
    int w0 = wt * 128;
    int tid = threadIdx.x;
    int og = tid >> 5;
    int wl = tid & 31;

    int rbase = (n * 12 + l) * 32;

    float acc[4][4];
#pragma unroll
    for (int j = 0; j < 4; j++) {
        float bj = bias[og * 4 + j];
#pragma unroll
        for (int i = 0; i < 4; i++) acc[j][i] = bj;
    }

    for (int k = 0; k < 7; k++) {
        if (k == 0) {
            for (int i = tid; i < 4096; i += 256) {
                int c = i >> 7, w = i & 127;
                Hs[c][w] = g_Xr[(size_t)(rbase + c) * 1024 + w0 + w];
            }
        } else {
            for (int i = tid; i < 4096; i += 256) {
                int c = i >> 7, w = i & 127;
                Hs[c][w] = g_Z[(size_t)(rbase + c) * 6144 + (k - 1) * 1024 + w0 + w];
            }
        }
        for (int i = tid; i < 1024; i += 256)
            Ws[i] = W[(i >> 5) * 224 + 32 * k + (i & 31)];
        __syncthreads();

#pragma unroll 4
        for (int c = 0; c < 32; c++) {
            float wv[4], hv[4];
#pragma unroll
            for (int j = 0; j < 4; j++) wv[j] = Ws[(og * 4 + j) * 32 + c];
#pragma unroll
            for (int i = 0; i < 4; i++) hv[i] = Hs[c][wl + 32 * i];
#pragma unroll
            for (int j = 0; j < 4; j++)
#pragma unroll
                for (int i = 0; i < 4; i++)
                    acc[j][i] = fmaf(wv[j], hv[i], acc[j][i]);
        }
        __syncthreads();
    }

#pragma unroll
    for (int j = 0; j < 4; j++) {
        int o = og * 4 + j;
#pragma unroll
        for (int i = 0; i < 4; i++) {
            int w = w0 + wl + 32 * i;
            out[((size_t)(n * 32 + o) * 1024 + w) * 12 + l] = acc[j][i];
        }
    }
}

// -------------------------------- launch ----------------------------------------
extern "C" void kernel_launch(void* const* d_in, const int* in_sizes, int n_in,
                              void* d_out, int out_size) {
    const float* x   = (const float*)d_in[0];
    const float* A1  = (const float*)d_in[1];
    const float* A2  = (const float*)d_in[2];
    const float* nv1 = (const float*)d_in[3];
    const float* nv2 = (const float*)d_in[4];
    const float* W   = (const float*)d_in[5];
    const float* b   = (const float*)d_in[6];
    float* out = (float*)d_out;

    cudaFuncSetAttribute(gemm_mma, cudaFuncAttributeMaxDynamicSharedMemorySize, GEMM_SMEM);

    adp_kernel<<<1024, 256>>>(nv1, nv2);
    copy_slots_T<<<dim3(32, 32, 3), dim3(32, 8)>>>(A1, A2);
    squares_T_kernel<<<dim3(8, 8, 3), 256>>>();
    convert_m<<<24576, 256>>>();
    transpose_x<<<dim3(4, 32, 64), 256>>>(x);
    gemm_mma<<<dim3(24, 192), 512, GEMM_SMEM>>>();
    epilogue_kernel<<<dim3(96, 64), 256>>>(W, b, out);
}